// round 17
// baseline (speedup 1.0000x reference)
#include <cuda_runtime.h>
#include <cuda_bf16.h>
#include <cstdint>
#include <math.h>

#define BDIM   16384
#define IN_DIM 4096
#define H1D    128
#define H2D    64
#define LAT    32
#define NREPS  3
#define SROW   80        // bf16 smem row stride (bytes) for gemm2
#define SROW4  144       // tf32 smem row stride (bytes): 36 floats, conflict-free

// ---------------------------------------------------------------------------
// Scratch (__device__ globals: allocation-free rule)
// ---------------------------------------------------------------------------
__device__ float g_h1[(size_t)BDIM * H1D];                            // 8 MB
__device__ __align__(16) float g_W1t_f[(size_t)H1D * IN_DIM];         // W1^T tf32-rounded, 2 MB
__device__ __align__(16) __nv_bfloat16 g_q_h[(size_t)BDIM * LAT];
__device__ __align__(16) __nv_bfloat16 g_q_l[(size_t)BDIM * LAT];
__device__ __align__(16) __nv_bfloat16 g_Wdt_h[(size_t)IN_DIM * LAT]; // Wd^T [n][k]
__device__ __align__(16) __nv_bfloat16 g_Wdt_l[(size_t)IN_DIM * LAT];

// ---------------------------------------------------------------------------
// Helpers (baseline PTX only: ldmatrix + mma.sync, sm_80-compatible)
// ---------------------------------------------------------------------------
__device__ __forceinline__ uint32_t smem_u32(const void* p) {
    uint32_t a;
    asm("{ .reg .u64 t; cvta.to.shared.u64 t, %1; cvt.u32.u64 %0, t; }" : "=r"(a) : "l"(p));
    return a;
}
__device__ __forceinline__ void ldsm_x4(uint32_t* r, uint32_t addr) {
    asm volatile("ldmatrix.sync.aligned.m8n8.x4.shared.b16 {%0,%1,%2,%3}, [%4];"
                 : "=r"(r[0]), "=r"(r[1]), "=r"(r[2]), "=r"(r[3]) : "r"(addr));
}
__device__ __forceinline__ void ldsm_x2(uint32_t* r, uint32_t addr) {
    asm volatile("ldmatrix.sync.aligned.m8n8.x2.shared.b16 {%0,%1}, [%2];"
                 : "=r"(r[0]), "=r"(r[1]) : "r"(addr));
}
__device__ __forceinline__ void mma16816(float* c, const uint32_t* a, const uint32_t* b) {
    asm volatile("mma.sync.aligned.m16n8k16.row.col.f32.bf16.bf16.f32 "
                 "{%0,%1,%2,%3}, {%4,%5,%6,%7}, {%8,%9}, {%0,%1,%2,%3};"
                 : "+f"(c[0]), "+f"(c[1]), "+f"(c[2]), "+f"(c[3])
                 : "r"(a[0]), "r"(a[1]), "r"(a[2]), "r"(a[3]), "r"(b[0]), "r"(b[1]));
}
__device__ __forceinline__ void mma1688_tf32(float* c, const uint32_t* a, const uint32_t* b) {
    asm volatile("mma.sync.aligned.m16n8k8.row.col.f32.tf32.tf32.f32 "
                 "{%0,%1,%2,%3}, {%4,%5,%6,%7}, {%8,%9}, {%0,%1,%2,%3};"
                 : "+f"(c[0]), "+f"(c[1]), "+f"(c[2]), "+f"(c[3])
                 : "r"(a[0]), "r"(a[1]), "r"(a[2]), "r"(a[3]), "r"(b[0]), "r"(b[1]));
}
__device__ __forceinline__ uint32_t f2tf32(float f) {
    uint32_t r;
    asm("cvt.rna.tf32.f32 %0, %1;" : "=r"(r) : "f"(f));
    return r;
}
__device__ __forceinline__ uint32_t pack_bf16x2(__nv_bfloat16 a, __nv_bfloat16 b) {
    return (uint32_t)__bfloat16_as_ushort(a) | ((uint32_t)__bfloat16_as_ushort(b) << 16);
}
__device__ __forceinline__ void split_bf16(float v, __nv_bfloat16& hi, __nv_bfloat16& lo) {
    hi = __float2bfloat16_rn(v);
    lo = __float2bfloat16_rn(v - __bfloat162float(hi));
}

// ---------------------------------------------------------------------------
// Merged prep: y<4 -> W1^T tf32-rounded float; y==4 -> Wd^T hi/lo bf16 split.
// ---------------------------------------------------------------------------
__global__ void k_prep(const float* __restrict__ W1, const float* __restrict__ Wd) {
    __shared__ float t[32][33];
    const int tx = threadIdx.x, ty = threadIdx.y;   // (32, 8)
    if (blockIdx.y < 4) {
        const int k0 = blockIdx.x * 32, n0 = blockIdx.y * 32;
        #pragma unroll
        for (int i = 0; i < 4; i++)
            t[ty + 8 * i][tx] = W1[(size_t)(k0 + ty + 8 * i) * H1D + n0 + tx];
        __syncthreads();
        #pragma unroll
        for (int i = 0; i < 4; i++) {
            const int n = n0 + ty + 8 * i, k = k0 + tx;
            g_W1t_f[(size_t)n * IN_DIM + k] = __uint_as_float(f2tf32(t[tx][ty + 8 * i]));
        }
    } else {
        const int n0 = blockIdx.x * 32;
        #pragma unroll
        for (int i = 0; i < 4; i++)
            t[ty + 8 * i][tx] = Wd[(size_t)(ty + 8 * i) * IN_DIM + n0 + tx];
        __syncthreads();
        #pragma unroll
        for (int i = 0; i < 4; i++) {
            const int n = n0 + ty + 8 * i, k = tx;
            __nv_bfloat16 h, l;
            split_bf16(t[tx][ty + 8 * i], h, l);
            g_Wdt_h[(size_t)n * LAT + k] = h;
            g_Wdt_l[(size_t)n * LAT + k] = l;
        }
    }
}

// ---------------------------------------------------------------------------
// GEMM1 (tf32 mma.sync): h1 = relu(x @ W1 + b1)   [exact R16 version]
// ---------------------------------------------------------------------------
__global__ __launch_bounds__(256) void k_gemm1_mma(const float* __restrict__ x,
                                                   const float* __restrict__ b1)
{
    __shared__ __align__(128) char sm[2 * 128 * SROW4];   // A (18 KB) + B (18 KB)
    char* sA = sm;
    char* sB = sm + 128 * SROW4;
    const uint32_t uA = smem_u32(sA), uB = smem_u32(sB);

    const int tid  = threadIdx.x;
    const int lane = tid & 31, wid = tid >> 5;
    const int wm = wid >> 2, wn = wid & 3;         // warp grid 2(m) x 4(n)
    const int r = tid >> 1, h = tid & 1;           // load role: row, k-half
    const int row0 = blockIdx.x * 128;

    float acc[4][4][4];
    #pragma unroll
    for (int im = 0; im < 4; im++)
        #pragma unroll
        for (int in = 0; in < 4; in++)
            #pragma unroll
            for (int j = 0; j < 4; j++) acc[im][in][j] = 0.f;

    const float* xp = &x[(size_t)(row0 + r) * IN_DIM + h * 16];
    const float* wp = &g_W1t_f[(size_t)r * IN_DIM + h * 16];

    // prefetch iter 0
    float4 xa[4], wa[4];
    #pragma unroll
    for (int j = 0; j < 4; j++) { xa[j] = *(const float4*)(xp + j * 4); wa[j] = *(const float4*)(wp + j * 4); }

    const uint32_t sts = (uint32_t)(r * SROW4 + h * 64);

    const int l7  = lane & 7;
    const int l8  = (lane >> 3) & 1;
    const int lhi = lane >> 4;
    const uint32_t aBase = uA + (uint32_t)((wm * 64 + l7 + l8 * 8) * SROW4) + (uint32_t)(lhi * 16);
    const uint32_t bBase = uB + (uint32_t)((wn * 32 + l7) * SROW4) + (uint32_t)(l8 * 16);

    for (int i = 0; i < IN_DIM / 32; ++i) {
        {
            uint32_t c0[4], c1[4], c2[4], c3[4];
            c0[0]=f2tf32(xa[0].x); c0[1]=f2tf32(xa[0].y); c0[2]=f2tf32(xa[0].z); c0[3]=f2tf32(xa[0].w);
            c1[0]=f2tf32(xa[1].x); c1[1]=f2tf32(xa[1].y); c1[2]=f2tf32(xa[1].z); c1[3]=f2tf32(xa[1].w);
            c2[0]=f2tf32(xa[2].x); c2[1]=f2tf32(xa[2].y); c2[2]=f2tf32(xa[2].z); c2[3]=f2tf32(xa[2].w);
            c3[0]=f2tf32(xa[3].x); c3[1]=f2tf32(xa[3].y); c3[2]=f2tf32(xa[3].z); c3[3]=f2tf32(xa[3].w);
            *(uint4*)(sA + sts)      = make_uint4(c0[0], c0[1], c0[2], c0[3]);
            *(uint4*)(sA + sts + 16) = make_uint4(c1[0], c1[1], c1[2], c1[3]);
            *(uint4*)(sA + sts + 32) = make_uint4(c2[0], c2[1], c2[2], c2[3]);
            *(uint4*)(sA + sts + 48) = make_uint4(c3[0], c3[1], c3[2], c3[3]);
            *(float4*)(sB + sts)      = wa[0];
            *(float4*)(sB + sts + 16) = wa[1];
            *(float4*)(sB + sts + 32) = wa[2];
            *(float4*)(sB + sts + 48) = wa[3];
        }
        __syncthreads();

        if (i < IN_DIM / 32 - 1) {
            const int off = (i + 1) * 32;
            #pragma unroll
            for (int j = 0; j < 4; j++) {
                xa[j] = *(const float4*)(xp + off + j * 4);
                wa[j] = *(const float4*)(wp + off + j * 4);
            }
        }

        #pragma unroll
        for (int ks = 0; ks < 4; ks++) {            // 4 k8-steps
            uint32_t a[4][4], b[4][2];
            #pragma unroll
            for (int im = 0; im < 4; im++)
                ldsm_x4(a[im], aBase + (uint32_t)(im * 16 * SROW4) + (uint32_t)(ks * 32));
            #pragma unroll
            for (int in = 0; in < 4; in++)
                ldsm_x2(b[in], bBase + (uint32_t)(in * 8 * SROW4) + (uint32_t)(ks * 32));
            #pragma unroll
            for (int im = 0; im < 4; im++)
                #pragma unroll
                for (int in = 0; in < 4; in++)
                    mma1688_tf32(acc[im][in], a[im], b[in]);
        }
        __syncthreads();
    }

    // epilogue: bias + relu -> g_h1
    #pragma unroll
    for (int im = 0; im < 4; im++) {
        const int rowa = row0 + wm * 64 + im * 16 + (lane >> 2);
        #pragma unroll
        for (int in = 0; in < 4; in++) {
            const int col = wn * 32 + in * 8 + 2 * (lane & 3);
            const float bb0 = b1[col], bb1 = b1[col + 1];
            float2 v0 = make_float2(fmaxf(acc[im][in][0] + bb0, 0.f),
                                    fmaxf(acc[im][in][1] + bb1, 0.f));
            float2 v1 = make_float2(fmaxf(acc[im][in][2] + bb0, 0.f),
                                    fmaxf(acc[im][in][3] + bb1, 0.f));
            *(float2*)&g_h1[(size_t)rowa * H1D + col]       = v0;
            *(float2*)&g_h1[(size_t)(rowa + 8) * H1D + col] = v1;
        }
    }
}

// ---------------------------------------------------------------------------
// Head v3: j-across-lanes layout (R5, unchanged).
// ---------------------------------------------------------------------------
__global__ __launch_bounds__(256) void k_head(const float* __restrict__ W2,
                                              const float* __restrict__ b2,
                                              const float* __restrict__ W3,
                                              const float* __restrict__ b3,
                                              const float* __restrict__ qparams)
{
    __shared__ float h1s[64][132];
    __shared__ float h2s[64][68];

    const int row0 = blockIdx.x * 64;
    const int tid  = threadIdx.x;

    #pragma unroll
    for (int i = 0; i < 8; i++) {
        const int f = tid + 256 * i;
        const int r = f >> 5, c4 = (f & 31) << 2;
        *(float4*)&h1s[r][c4] = *(const float4*)&g_h1[(size_t)(row0 + r) * H1D + c4];
    }
    __syncthreads();

    {
        const int j  = tid & 63;
        const int rg = tid >> 6;
        float acc[16];
        const float bj = b2[j];
        #pragma unroll
        for (int t = 0; t < 16; t++) acc[t] = bj;

        #pragma unroll 4
        for (int k = 0; k < H1D; k++) {
            const float w = W2[k * H2D + j];
            #pragma unroll
            for (int t = 0; t < 16; t++)
                acc[t] = fmaf(h1s[rg * 16 + t][k], w, acc[t]);
        }
        #pragma unroll
        for (int t = 0; t < 16; t++)
            h2s[rg * 16 + t][j] = fmaxf(acc[t], 0.f);
    }
    __syncthreads();

    {
        const int j2  = tid & 31;
        const int rg2 = tid >> 5;
        float base = b3[j2];
        #pragma unroll
        for (int rep = 0; rep < 2 * NREPS; rep++)
            base += qparams[rep * LAT + j2];

        float z[8];
        #pragma unroll
        for (int t = 0; t < 8; t++) z[t] = base;

        #pragma unroll 4
        for (int k = 0; k < H2D; k++) {
            const float w = W3[k * LAT + j2];
            #pragma unroll
            for (int t = 0; t < 8; t++)
                z[t] = fmaf(h2s[rg2 * 8 + t][k], w, z[t]);
        }

        #pragma unroll
        for (int t = 0; t < 8; t++) {
            const int row = row0 + rg2 * 8 + t;
            const float qv = cosf(z[t]);
            __nv_bfloat16 hh, ll;
            split_bf16(qv, hh, ll);
            g_q_h[(size_t)row * LAT + j2] = hh;
            g_q_l[(size_t)row * LAT + j2] = ll;
        }
    }
}

// ---------------------------------------------------------------------------
// GEMM2 (mma.sync bf16): out = q @ Wd + bd.  CTA tile 128x128, K=32.
// R5 mainloop + NEW coalesced epilogue: per-warp smem transpose of the
// C-subtile so every STG is a full 128B line (4 wavefronts/instr vs 8/STG.64).
// ---------------------------------------------------------------------------
#define EPI_ROWSTRIDE 36   // floats; 144B, 16B-aligned, conflict-free LDS.128
__global__ __launch_bounds__(256) void k_gemm2_mma(const float* __restrict__ bd,
                                                   float* __restrict__ out)
{
    __shared__ __align__(128) char sm[4 * 128 * SROW];
    char* sQh = sm;
    char* sQl = sm + 128 * SROW;
    char* sWh = sm + 2 * 128 * SROW;
    char* sWl = sm + 3 * 128 * SROW;
    const uint32_t uQh = smem_u32(sQh), uQl = smem_u32(sQl);
    const uint32_t uWh = smem_u32(sWh), uWl = smem_u32(sWl);

    const int tid  = threadIdx.x;
    const int lane = tid & 31, wid = tid >> 5;
    const int wm = wid >> 2, wn = wid & 3;
    const int r = tid >> 1, h = tid & 1;
    const int n0 = blockIdx.x * 128;
    const int m0 = blockIdx.y * 128;

    const uint32_t sts = (uint32_t)(r * SROW + h * 32);
    {
        const __nv_bfloat16* qh = &g_q_h[(size_t)(m0 + r) * LAT + h * 16];
        const __nv_bfloat16* ql = &g_q_l[(size_t)(m0 + r) * LAT + h * 16];
        const __nv_bfloat16* wh = &g_Wdt_h[(size_t)(n0 + r) * LAT + h * 16];
        const __nv_bfloat16* wl = &g_Wdt_l[(size_t)(n0 + r) * LAT + h * 16];
        *(uint4*)(sQh + sts)      = *(const uint4*)qh;
        *(uint4*)(sQh + sts + 16) = *(const uint4*)(qh + 8);
        *(uint4*)(sQl + sts)      = *(const uint4*)ql;
        *(uint4*)(sQl + sts + 16) = *(const uint4*)(ql + 8);
        *(uint4*)(sWh + sts)      = *(const uint4*)wh;
        *(uint4*)(sWh + sts + 16) = *(const uint4*)(wh + 8);
        *(uint4*)(sWl + sts)      = *(const uint4*)wl;
        *(uint4*)(sWl + sts + 16) = *(const uint4*)(wl + 8);
    }
    __syncthreads();

    float acc[4][4][4];
    #pragma unroll
    for (int im = 0; im < 4; im++)
        #pragma unroll
        for (int in = 0; in < 4; in++)
            #pragma unroll
            for (int j = 0; j < 4; j++) acc[im][in][j] = 0.f;

    #pragma unroll
    for (int ks = 0; ks < 2; ks++) {
        uint32_t ah[4][4], al[4][4], bh[4][2], bl[4][2];
        const uint32_t akb = (uint32_t)(ks * 32 + (lane >> 4) * 16 + (lane & 15) * SROW);
        #pragma unroll
        for (int im = 0; im < 4; im++) {
            const uint32_t mo = (uint32_t)((wm * 64 + im * 16) * SROW) + akb;
            ldsm_x4(ah[im], uQh + mo);
            ldsm_x4(al[im], uQl + mo);
        }
        const uint32_t bkb = (uint32_t)(ks * 32 + ((lane >> 3) & 1) * 16 + (lane & 7) * SROW);
        #pragma unroll
        for (int in = 0; in < 4; in++) {
            const uint32_t no = (uint32_t)((wn * 32 + in * 8) * SROW) + bkb;
            ldsm_x2(bh[in], uWh + no);
            ldsm_x2(bl[in], uWl + no);
        }
        #pragma unroll
        for (int im = 0; im < 4; im++)
            #pragma unroll
            for (int in = 0; in < 4; in++) {
                mma16816(acc[im][in], ah[im], bh[in]);
                mma16816(acc[im][in], ah[im], bl[in]);
                mma16816(acc[im][in], al[im], bh[in]);
            }
    }

    // all warps done reading operand smem before we overwrite it
    __syncthreads();

    // coalesced epilogue: per-warp 16x32 staging buffer (2304B each, 18KB total)
    {
        float* wbuf = (float*)(sm + wid * (16 * EPI_ROWSTRIDE * 4));
        const int lg = lane >> 2;          // 0..7
        const int lk = 2 * (lane & 3);     // 0,2,4,6
        const float bd0 = bd[n0 + wn * 32 + (lane & 7) * 4 + 0];
        const float bd1 = bd[n0 + wn * 32 + (lane & 7) * 4 + 1];
        const float bd2 = bd[n0 + wn * 32 + (lane & 7) * 4 + 2];
        const float bd3 = bd[n0 + wn * 32 + (lane & 7) * 4 + 3];

        #pragma unroll
        for (int im = 0; im < 4; im++) {
            // scatter acc into the staging tile
            #pragma unroll
            for (int in = 0; in < 4; in++) {
                const int c = in * 8 + lk;
                *(float2*)&wbuf[lg * EPI_ROWSTRIDE + c]       = make_float2(acc[im][in][0], acc[im][in][1]);
                *(float2*)&wbuf[(lg + 8) * EPI_ROWSTRIDE + c] = make_float2(acc[im][in][2], acc[im][in][3]);
            }
            __syncwarp();
            // coalesced read-out + bias + STG.128 (full 128B lines)
            #pragma unroll
            for (int p = 0; p < 4; p++) {
                const int rr  = p * 4 + (lane >> 3);      // 0..15
                const int grp = lane & 7;                 // float4 group
                float4 v = *(float4*)&wbuf[rr * EPI_ROWSTRIDE + grp * 4];
                v.x += bd0; v.y += bd1; v.z += bd2; v.w += bd3;
                const int rowa = m0 + wm * 64 + im * 16 + rr;
                const int col  = n0 + wn * 32 + grp * 4;
                *(float4*)&out[(size_t)rowa * IN_DIM + col] = v;
            }
            __syncwarp();
        }
    }
}

// ---------------------------------------------------------------------------
extern "C" void kernel_launch(void* const* d_in, const int* in_sizes, int n_in,
                              void* d_out, int out_size)
{
    const float* x  = (const float*)d_in[0];
    const float* W1 = (const float*)d_in[1];
    const float* b1 = (const float*)d_in[2];
    const float* W2 = (const float*)d_in[3];
    const float* b2 = (const float*)d_in[4];
    const float* W3 = (const float*)d_in[5];
    const float* b3 = (const float*)d_in[6];
    const float* qp = (const float*)d_in[7];
    const float* Wd = (const float*)d_in[8];
    const float* bd = (const float*)d_in[9];
    float* out = (float*)d_out;

    k_prep<<<dim3(IN_DIM / 32, 5), dim3(32, 8)>>>(W1, Wd);
    k_gemm1_mma<<<BDIM / 128, 256>>>(x, b1);
    k_head<<<BDIM / 64, 256>>>(W2, b2, W3, b3, qp);
    k_gemm2_mma<<<dim3(IN_DIM / 128, BDIM / 128), 256>>>(bd, out);
}